// round 1
// baseline (speedup 1.0000x reference)
#include <cuda_runtime.h>

#define Bq 8
#define Nq 1024
#define Cq 1024
#define Hq 16
#define Dq 64

// Scratch (static device globals; no allocation)
__device__ float g_q[Bq * Hq * Nq * Dq];
__device__ float g_k[Bq * Hq * Nq * Dq];
__device__ float g_v[Bq * Hq * Nq * Dq];
__device__ float g_ctx[Bq * Nq * Cq];

// ---------------------------------------------------------------------------
// NT GEMM: C[m][n] = sum_k A[m][k]*B[n][k] + bias[n]
// 128x128 tile, BK=8, 256 threads, 8x8 micro-tile (4x4 quadrants), reg prefetch.
// MODE 1: epilogue scatters into g_q (scaled by 1/8), g_k, g_v.
// MODE 2: A is g_ctx (device global), plain epilogue to C.
// ---------------------------------------------------------------------------
template <int MODE>
__global__ __launch_bounds__(256) void gemm_nt(
    const float* __restrict__ A, const float* __restrict__ Bm,
    const float* __restrict__ bias, float* __restrict__ C,
    int M, int N, int K)
{
    __shared__ float As[8][128];
    __shared__ float Bs[8][128];

    const float* Abase = (MODE == 2) ? g_ctx : A;

    int t  = threadIdx.x;
    int m0 = blockIdx.y * 128;
    int n0 = blockIdx.x * 128;
    int tx = t & 15;       // 0..15 (n direction)
    int ty = t >> 4;       // 0..15 (m direction)
    int lr = t >> 1;       // 0..127 (tile row for loads)
    int lc = (t & 1) << 2; // 0 or 4 (k offset for loads)

    const float* Ag = Abase + (long)(m0 + lr) * K + lc;
    const float* Bg = Bm    + (long)(n0 + lr) * K + lc;

    float acc[8][8];
#pragma unroll
    for (int i = 0; i < 8; i++)
#pragma unroll
        for (int j = 0; j < 8; j++) acc[i][j] = 0.f;

    float4 pa = *(const float4*)Ag;
    float4 pb = *(const float4*)Bg;
    int nk = K >> 3;

    for (int kt = 0; kt < nk; kt++) {
        As[lc + 0][lr] = pa.x; As[lc + 1][lr] = pa.y;
        As[lc + 2][lr] = pa.z; As[lc + 3][lr] = pa.w;
        Bs[lc + 0][lr] = pb.x; Bs[lc + 1][lr] = pb.y;
        Bs[lc + 2][lr] = pb.z; Bs[lc + 3][lr] = pb.w;
        __syncthreads();

        if (kt + 1 < nk) {
            pa = *(const float4*)(Ag + (kt + 1) * 8);
            pb = *(const float4*)(Bg + (kt + 1) * 8);
        }

#pragma unroll
        for (int kk = 0; kk < 8; kk++) {
            float4 a0 = *(const float4*)&As[kk][ty * 4];
            float4 a1 = *(const float4*)&As[kk][ty * 4 + 64];
            float4 b0 = *(const float4*)&Bs[kk][tx * 4];
            float4 b1 = *(const float4*)&Bs[kk][tx * 4 + 64];
            float a[8] = {a0.x, a0.y, a0.z, a0.w, a1.x, a1.y, a1.z, a1.w};
            float b[8] = {b0.x, b0.y, b0.z, b0.w, b1.x, b1.y, b1.z, b1.w};
#pragma unroll
            for (int i = 0; i < 8; i++)
#pragma unroll
                for (int j = 0; j < 8; j++)
                    acc[i][j] = fmaf(a[i], b[j], acc[i][j]);
        }
        __syncthreads();
    }

#pragma unroll
    for (int i = 0; i < 8; i++) {
        int gm = m0 + ty * 4 + (i & 3) + ((i >> 2) << 6);
#pragma unroll
        for (int j = 0; j < 8; j++) {
            int gn = n0 + tx * 4 + (j & 3) + ((j >> 2) << 6);
            float val = acc[i][j] + __ldg(&bias[gn]);
            if (MODE == 1) {
                int bb = gm >> 10, nn = gm & 1023;
                int which = gn >> 10, hh = (gn >> 6) & 15, dd = gn & 63;
                int idx = ((bb * Hq + hh) * Nq + nn) * Dq + dd;
                if (which == 0)      g_q[idx] = val * 0.125f; // 1/sqrt(64)
                else if (which == 1) g_k[idx] = val;
                else                 g_v[idx] = val;
            } else {
                C[(long)gm * N + gn] = val;
            }
        }
    }
}

// ---------------------------------------------------------------------------
// Flash attention, fp32 SIMT.
// grid = (N/64, B*H), 256 threads. Each block: 64 query rows x D=64.
// Thread t: rowgroup g=t/16 handles rows {g, g+16, g+32, g+48};
//           lane=t%15.. keys {lane, lane+16, lane+32, lane+48} (score stage)
//           dims {lane*4 .. lane*4+3} (PV stage).
// ---------------------------------------------------------------------------
#define PAD 68
#define ATTN_SMEM (4 * 64 * PAD * (int)sizeof(float))

__global__ __launch_bounds__(256) void attn_kernel(const float* __restrict__ mask)
{
    extern __shared__ float sm[];
    float* Qs = sm;
    float* Ks = Qs + 64 * PAD;
    float* Vs = Ks + 64 * PAD;
    float* Ps = Vs + 64 * PAD;

    int t    = threadIdx.x;
    int lane = t & 15;
    int g    = t >> 4;
    int qt   = blockIdx.x;  // query tile 0..15
    int bh   = blockIdx.y;  // 0..127

    const float* Qg = g_q + ((long)bh * Nq + qt * 64) * Dq;
    const float* Kg = g_k + (long)bh * Nq * Dq;
    const float* Vg = g_v + (long)bh * Nq * Dq;

    // Load Q tile (64x64) into padded smem
    for (int i = t; i < 1024; i += 256) {
        int row = i >> 4, c4 = (i & 15) << 2;
        *(float4*)&Qs[row * PAD + c4] = *(const float4*)(Qg + row * 64 + c4);
    }

    float mrow[4], lrow[4], o[4][4];
#pragma unroll
    for (int i = 0; i < 4; i++) {
        mrow[i] = -1e30f;
        lrow[i] = 0.f;
#pragma unroll
        for (int j = 0; j < 4; j++) o[i][j] = 0.f;
    }

    for (int kt = 0; kt < 16; kt++) {
        const float4* Kt = (const float4*)(Kg + kt * 64 * 64);
        const float4* Vt = (const float4*)(Vg + kt * 64 * 64);
        for (int i = t; i < 1024; i += 256) {
            int row = i >> 4, c4 = (i & 15) << 2;
            *(float4*)&Ks[row * PAD + c4] = Kt[i];
            *(float4*)&Vs[row * PAD + c4] = Vt[i];
        }
        __syncthreads();

        // ---- scores: s[i][j] = q(row_i) . k(key_j) ----
        float s[4][4];
#pragma unroll
        for (int i = 0; i < 4; i++)
#pragma unroll
            for (int j = 0; j < 4; j++) s[i][j] = 0.f;

        for (int d4 = 0; d4 < 64; d4 += 4) {
            float4 av[4], bv[4];
#pragma unroll
            for (int i = 0; i < 4; i++)
                av[i] = *(const float4*)&Qs[(g + 16 * i) * PAD + d4];
#pragma unroll
            for (int j = 0; j < 4; j++)
                bv[j] = *(const float4*)&Ks[(lane + 16 * j) * PAD + d4];
#pragma unroll
            for (int i = 0; i < 4; i++)
#pragma unroll
                for (int j = 0; j < 4; j++) {
                    s[i][j] = fmaf(av[i].x, bv[j].x, s[i][j]);
                    s[i][j] = fmaf(av[i].y, bv[j].y, s[i][j]);
                    s[i][j] = fmaf(av[i].z, bv[j].z, s[i][j]);
                    s[i][j] = fmaf(av[i].w, bv[j].w, s[i][j]);
                }
        }

        // ---- mask + online softmax ----
        int qbase = qt * 64, kbase = kt * 64;
#pragma unroll
        for (int i = 0; i < 4; i++) {
            int qr = qbase + g + 16 * i;
#pragma unroll
            for (int j = 0; j < 4; j++)
                s[i][j] += __ldg(&mask[(long)qr * Nq + kbase + lane + 16 * j]);

            float mx = fmaxf(fmaxf(s[i][0], s[i][1]), fmaxf(s[i][2], s[i][3]));
            mx = fmaxf(mx, __shfl_xor_sync(0xffffffffu, mx, 8));
            mx = fmaxf(mx, __shfl_xor_sync(0xffffffffu, mx, 4));
            mx = fmaxf(mx, __shfl_xor_sync(0xffffffffu, mx, 2));
            mx = fmaxf(mx, __shfl_xor_sync(0xffffffffu, mx, 1));
            float newm = fmaxf(mrow[i], mx);
            float alpha = __expf(mrow[i] - newm);
            mrow[i] = newm;

            float rs = 0.f;
#pragma unroll
            for (int j = 0; j < 4; j++) {
                s[i][j] = __expf(s[i][j] - newm);
                rs += s[i][j];
            }
            rs += __shfl_xor_sync(0xffffffffu, rs, 8);
            rs += __shfl_xor_sync(0xffffffffu, rs, 4);
            rs += __shfl_xor_sync(0xffffffffu, rs, 2);
            rs += __shfl_xor_sync(0xffffffffu, rs, 1);
            lrow[i] = lrow[i] * alpha + rs;

#pragma unroll
            for (int j = 0; j < 4; j++) o[i][j] *= alpha;
#pragma unroll
            for (int j = 0; j < 4; j++)
                Ps[(g + 16 * i) * PAD + lane + 16 * j] = s[i][j];
        }
        __syncthreads();

        // ---- PV: o[row_i][dim_j] += sum_k P[row][k] * V[k][dim] ----
        for (int k0 = 0; k0 < 64; k0 += 4) {
            float4 p4[4];
#pragma unroll
            for (int i = 0; i < 4; i++)
                p4[i] = *(const float4*)&Ps[(g + 16 * i) * PAD + k0];
#pragma unroll
            for (int kk = 0; kk < 4; kk++) {
                float4 vv = *(const float4*)&Vs[(k0 + kk) * PAD + lane * 4];
#pragma unroll
                for (int i = 0; i < 4; i++) {
                    float pk = (kk == 0) ? p4[i].x
                             : (kk == 1) ? p4[i].y
                             : (kk == 2) ? p4[i].z
                                         : p4[i].w;
                    o[i][0] = fmaf(pk, vv.x, o[i][0]);
                    o[i][1] = fmaf(pk, vv.y, o[i][1]);
                    o[i][2] = fmaf(pk, vv.z, o[i][2]);
                    o[i][3] = fmaf(pk, vv.w, o[i][3]);
                }
            }
        }
        __syncthreads();
    }

    // ---- epilogue: ctx layout (B, N, H*D) ----
    int bb = bh >> 4, hh = bh & 15;
#pragma unroll
    for (int i = 0; i < 4; i++) {
        float inv = 1.f / lrow[i];
        int n = qt * 64 + g + 16 * i;
        float* dst = g_ctx + ((long)(bb * Nq + n)) * Cq + hh * 64 + lane * 4;
        float4 ov = make_float4(o[i][0] * inv, o[i][1] * inv,
                                o[i][2] * inv, o[i][3] * inv);
        *(float4*)dst = ov;
    }
}

// ---------------------------------------------------------------------------
extern "C" void kernel_launch(void* const* d_in, const int* in_sizes, int n_in,
                              void* d_out, int out_size)
{
    const float* x    = (const float*)d_in[0]; // (B,N,C)
    const float* mask = (const float*)d_in[1]; // (N,N)
    const float* W    = (const float*)d_in[2]; // (3C, C)
    const float* bia  = (const float*)d_in[3]; // (3C)
    const float* ow   = (const float*)d_in[4]; // (C, C)
    const float* ob   = (const float*)d_in[5]; // (C)
    float* out = (float*)d_out;

    // 1) QKV projection: (8192 x 3072 x 1024), scatter into g_q/g_k/g_v
    gemm_nt<1><<<dim3(3072 / 128, 8192 / 128), 256>>>(
        x, W, bia, nullptr, Bq * Nq, 3 * Cq, Cq);

    // 2) Attention
    cudaFuncSetAttribute(attn_kernel,
                         cudaFuncAttributeMaxDynamicSharedMemorySize, ATTN_SMEM);
    attn_kernel<<<dim3(Nq / 64, Bq * Hq), 256, ATTN_SMEM>>>(mask);

    // 3) Output projection: (8192 x 1024 x 1024) from g_ctx
    gemm_nt<2><<<dim3(1024 / 128, 8192 / 128), 256>>>(
        nullptr, ow, ob, out, Bq * Nq, Cq, Cq);
}

// round 3
// speedup vs baseline: 1.4138x; 1.4138x over previous
#include <cuda_runtime.h>
#include <cuda_bf16.h>
#include <cstdint>

#define Bq 8
#define Nq 1024
#define Cq 1024
#define Hq 16
#define Dq 64

// ---------------- scratch (static device globals; no allocation) ----------------
__device__ float g_q[Bq * Hq * Nq * Dq];
__device__ float g_k[Bq * Hq * Nq * Dq];
__device__ float g_v[Bq * Hq * Nq * Dq];
__device__ float g_ctx[Bq * Nq * Cq];

__device__ __align__(16) __nv_bfloat16 g_xhi[Bq * Nq * Cq],  g_xlo[Bq * Nq * Cq];
__device__ __align__(16) __nv_bfloat16 g_whi[3 * Cq * Cq],   g_wlo[3 * Cq * Cq];
__device__ __align__(16) __nv_bfloat16 g_owhi[Cq * Cq],      g_owlo[Cq * Cq];
__device__ __align__(16) __nv_bfloat16 g_chi[Bq * Nq * Cq],  g_clo[Bq * Nq * Cq];

// ---------------- PTX helpers (sm_80+ only; no tcgen05) ----------------
__device__ __forceinline__ uint32_t smem_u32(const void* p) {
    uint32_t a;
    asm("{ .reg .u64 t; cvta.to.shared.u64 t, %1; cvt.u32.u64 %0, t; }" : "=r"(a) : "l"(p));
    return a;
}
__device__ __forceinline__ void cp16(uint32_t dst, const void* src) {
    asm volatile("cp.async.cg.shared.global [%0], [%1], 16;" :: "r"(dst), "l"(src) : "memory");
}
__device__ __forceinline__ void cp_commit() {
    asm volatile("cp.async.commit_group;" ::: "memory");
}
template <int N>
__device__ __forceinline__ void cp_wait() {
    asm volatile("cp.async.wait_group %0;" :: "n"(N) : "memory");
}
__device__ __forceinline__ void ldsm4(uint32_t& r0, uint32_t& r1, uint32_t& r2, uint32_t& r3,
                                      uint32_t addr) {
    asm volatile("ldmatrix.sync.aligned.m8n8.x4.shared.b16 {%0,%1,%2,%3}, [%4];"
                 : "=r"(r0), "=r"(r1), "=r"(r2), "=r"(r3) : "r"(addr));
}
__device__ __forceinline__ void mma16816(float* c, const uint32_t* a, const uint32_t* b) {
    asm volatile("mma.sync.aligned.m16n8k16.row.col.f32.bf16.bf16.f32 "
                 "{%0,%1,%2,%3}, {%4,%5,%6,%7}, {%8,%9}, {%0,%1,%2,%3};"
                 : "+f"(c[0]), "+f"(c[1]), "+f"(c[2]), "+f"(c[3])
                 : "r"(a[0]), "r"(a[1]), "r"(a[2]), "r"(a[3]), "r"(b[0]), "r"(b[1]));
}

// swizzled offset within a 64-byte-row tile (conflict-free for 8-row ldmatrix)
__device__ __forceinline__ uint32_t swz(int row, int cbyte) {
    return (uint32_t)(row * 64 + (cbyte ^ (((row >> 1) & 3) << 4)));
}

// ---------------- fp32 -> bf16 hi/lo split ----------------
// T: 0 -> x, 1 -> in_proj_weight, 2 -> out_w, 3 -> g_ctx
template <int T>
__global__ __launch_bounds__(256) void conv_split(const float* __restrict__ src, int n)
{
    int i = (blockIdx.x * 256 + threadIdx.x) * 4;
    if (i >= n) return;
    const float* s = (T == 3) ? (const float*)g_ctx : src;
    float4 v = *(const float4*)(s + i);
    float vv[4] = {v.x, v.y, v.z, v.w};
    uint32_t hp[2], lp[2];
#pragma unroll
    for (int p = 0; p < 2; p++) {
        __nv_bfloat16 h0 = __float2bfloat16(vv[2*p]);
        __nv_bfloat16 h1 = __float2bfloat16(vv[2*p+1]);
        __nv_bfloat16 l0 = __float2bfloat16(vv[2*p]   - __bfloat162float(h0));
        __nv_bfloat16 l1 = __float2bfloat16(vv[2*p+1] - __bfloat162float(h1));
        hp[p] = (uint32_t)__bfloat16_as_ushort(h0) | ((uint32_t)__bfloat16_as_ushort(h1) << 16);
        lp[p] = (uint32_t)__bfloat16_as_ushort(l0) | ((uint32_t)__bfloat16_as_ushort(l1) << 16);
    }
    __nv_bfloat16* hd = (T == 0) ? g_xhi : (T == 1) ? g_whi : (T == 2) ? g_owhi : g_chi;
    __nv_bfloat16* ld = (T == 0) ? g_xlo : (T == 1) ? g_wlo : (T == 2) ? g_owlo : g_clo;
    *(uint2*)(hd + i) = make_uint2(hp[0], hp[1]);
    *(uint2*)(ld + i) = make_uint2(lp[0], lp[1]);
}

// ---------------- mma.sync split-bf16 NT GEMM ----------------
// C[m][n] = sum_k A[m][k]*B[n][k] + bias[n]
// MODE 1: A = x (hi/lo), B = W (hi/lo), N=3072 -> scatter to g_q/g_k/g_v
// MODE 2: A = ctx (hi/lo), B = ow (hi/lo), N=1024 -> Cout
// Block 128x128, BK=32 bf16, 256 threads (8 warps as 4Mx2N), warp tile 32x64.
// K-chunks: 96 = 3 terms x 32 chunks (term 0: hi*hi, 1: hi*lo, 2: lo*hi).
#define NCH2 96
#define STAGE_BYTES 16384   // A 128x32 bf16 (8KB) + B 128x32 bf16 (8KB)

template <int MODE>
__global__ __launch_bounds__(256) void gemm_mma(const float* __restrict__ bias,
                                                float* __restrict__ Cout)
{
    __shared__ __align__(1024) char smem[2][STAGE_BYTES];
    const uint32_t sb = smem_u32(smem);

    const int t = threadIdx.x, wid = t >> 5, lane = t & 31;
    const int m0 = blockIdx.y * 128, n0 = blockIdx.x * 128;
    const int wm = (wid & 3) * 32, wn = (wid >> 2) * 64;
    const int gid = lane >> 2, tid = lane & 3;

    float c[2][8][4];
#pragma unroll
    for (int mi = 0; mi < 2; mi++)
#pragma unroll
        for (int nj = 0; nj < 8; nj++)
#pragma unroll
            for (int r = 0; r < 4; r++) c[mi][nj][r] = 0.f;

    auto load_stage = [&](int ch, int buf) {
        const int term = ch >> 5;
        const int kk = (ch & 31) * 32;   // element offset in K
        const __nv_bfloat16* Asrc = (MODE == 1) ? (term < 2 ? g_xhi : g_xlo)
                                                : (term < 2 ? g_chi : g_clo);
        const __nv_bfloat16* Bsrc = (MODE == 1) ? (term == 1 ? g_wlo : g_whi)
                                                : (term == 1 ? g_owlo : g_owhi);
        uint32_t sa = sb + buf * STAGE_BYTES;
#pragma unroll
        for (int i = 0; i < 2; i++) {                 // A: 512 16B-chunks
            int chk = t + i * 256;
            int row = chk >> 2, ce = (chk & 3) * 8;   // 8 bf16 per 16B
            cp16(sa + swz(row, ce * 2),
                 Asrc + (long)(m0 + row) * 1024 + kk + ce);
        }
#pragma unroll
        for (int i = 0; i < 2; i++) {                 // B: 512 16B-chunks
            int chk = t + i * 256;
            int row = chk >> 2, ce = (chk & 3) * 8;
            cp16(sa + 8192 + swz(row, ce * 2),
                 Bsrc + (long)(n0 + row) * 1024 + kk + ce);
        }
    };

    // fragment address: lane-group mapping for ldmatrix.x4
    auto frag_addr = [&](uint32_t tilebase, int base_r, int kb) -> uint32_t {
        int r = base_r + (lane & 7) + ((lane >> 3) & 1) * 8;
        int cb = kb + ((lane >> 4) << 4);
        return tilebase + swz(r, cb);
    };

    load_stage(0, 0);
    cp_commit();

    for (int i = 0; i < NCH2; i++) {
        const int buf = i & 1;
        if (i + 1 < NCH2) {
            load_stage(i + 1, buf ^ 1);
            cp_commit();
            cp_wait<1>();
        } else {
            cp_wait<0>();
        }
        __syncthreads();

        const uint32_t abase = sb + buf * STAGE_BYTES;
        const uint32_t bbase = abase + 8192;
#pragma unroll
        for (int s = 0; s < 2; s++) {       // two k16 steps per BK=32
            const int kb = s * 32;          // byte offset in row
            uint32_t a[2][4];
#pragma unroll
            for (int mi = 0; mi < 2; mi++)
                ldsm4(a[mi][0], a[mi][1], a[mi][2], a[mi][3],
                      frag_addr(abase, wm + mi * 16, kb));
            uint32_t b[8][2];
#pragma unroll
            for (int j = 0; j < 4; j++) {
                uint32_t r0, r1, r2, r3;
                ldsm4(r0, r1, r2, r3, frag_addr(bbase, wn + j * 16, kb));
                b[2*j][0] = r0; b[2*j][1] = r2;
                b[2*j+1][0] = r1; b[2*j+1][1] = r3;
            }
#pragma unroll
            for (int mi = 0; mi < 2; mi++)
#pragma unroll
                for (int nj = 0; nj < 8; nj++)
                    mma16816(c[mi][nj], a[mi], b[nj]);
        }
        __syncthreads();
    }

    // ---- epilogue ----
#pragma unroll
    for (int mi = 0; mi < 2; mi++) {
#pragma unroll
        for (int nj = 0; nj < 8; nj++) {
            int row = m0 + wm + mi * 16 + gid;
            int col = n0 + wn + nj * 8 + tid * 2;
            float b0 = __ldg(&bias[col]), b1 = __ldg(&bias[col + 1]);
#pragma unroll
            for (int h = 0; h < 2; h++) {   // h=0: row, h=1: row+8
                int rr = row + h * 8;
                float vx = c[mi][nj][2*h + 0] + b0;
                float vy = c[mi][nj][2*h + 1] + b1;
                if (MODE == 1) {
                    int bb = rr >> 10, nn = rr & 1023;
                    int which = col >> 10, hh = (col >> 6) & 15, dd = col & 63;
                    long idx = ((long)(bb * Hq + hh) * Nq + nn) * Dq + dd;
                    if (which == 0)
                        *(float2*)(g_q + idx) = make_float2(vx * 0.125f, vy * 0.125f);
                    else if (which == 1)
                        *(float2*)(g_k + idx) = make_float2(vx, vy);
                    else
                        *(float2*)(g_v + idx) = make_float2(vx, vy);
                } else {
                    *(float2*)(Cout + (long)rr * Cq + col) = make_float2(vx, vy);
                }
            }
        }
    }
}

// ---------------- flash attention (fp32 SIMT, unchanged) ----------------
#define PAD 68
#define ATTN_SMEM (4 * 64 * PAD * (int)sizeof(float))

__global__ __launch_bounds__(256) void attn_kernel(const float* __restrict__ mask)
{
    extern __shared__ float sm[];
    float* Qs = sm;
    float* Ks = Qs + 64 * PAD;
    float* Vs = Ks + 64 * PAD;
    float* Ps = Vs + 64 * PAD;

    int t    = threadIdx.x;
    int lane = t & 15;
    int g    = t >> 4;
    int qt   = blockIdx.x;
    int bh   = blockIdx.y;

    const float* Qg = g_q + ((long)bh * Nq + qt * 64) * Dq;
    const float* Kg = g_k + (long)bh * Nq * Dq;
    const float* Vg = g_v + (long)bh * Nq * Dq;

    for (int i = t; i < 1024; i += 256) {
        int row = i >> 4, c4 = (i & 15) << 2;
        *(float4*)&Qs[row * PAD + c4] = *(const float4*)(Qg + row * 64 + c4);
    }

    float mrow[4], lrow[4], o[4][4];
#pragma unroll
    for (int i = 0; i < 4; i++) {
        mrow[i] = -1e30f;
        lrow[i] = 0.f;
#pragma unroll
        for (int j = 0; j < 4; j++) o[i][j] = 0.f;
    }

    for (int kt = 0; kt < 16; kt++) {
        const float4* Kt = (const float4*)(Kg + kt * 64 * 64);
        const float4* Vt = (const float4*)(Vg + kt * 64 * 64);
        for (int i = t; i < 1024; i += 256) {
            int row = i >> 4, c4 = (i & 15) << 2;
            *(float4*)&Ks[row * PAD + c4] = Kt[i];
            *(float4*)&Vs[row * PAD + c4] = Vt[i];
        }
        __syncthreads();

        float s[4][4];
#pragma unroll
        for (int i = 0; i < 4; i++)
#pragma unroll
            for (int j = 0; j < 4; j++) s[i][j] = 0.f;

        for (int d4 = 0; d4 < 64; d4 += 4) {
            float4 av[4], bv[4];
#pragma unroll
            for (int i = 0; i < 4; i++)
                av[i] = *(const float4*)&Qs[(g + 16 * i) * PAD + d4];
#pragma unroll
            for (int j = 0; j < 4; j++)
                bv[j] = *(const float4*)&Ks[(lane + 16 * j) * PAD + d4];
#pragma unroll
            for (int i = 0; i < 4; i++)
#pragma unroll
                for (int j = 0; j < 4; j++) {
                    s[i][j] = fmaf(av[i].x, bv[j].x, s[i][j]);
                    s[i][j] = fmaf(av[i].y, bv[j].y, s[i][j]);
                    s[i][j] = fmaf(av[i].z, bv[j].z, s[i][j]);
                    s[i][j] = fmaf(av[i].w, bv[j].w, s[i][j]);
                }
        }

        int qbase = qt * 64, kbase = kt * 64;
#pragma unroll
        for (int i = 0; i < 4; i++) {
            int qr = qbase + g + 16 * i;
#pragma unroll
            for (int j = 0; j < 4; j++)
                s[i][j] += __ldg(&mask[(long)qr * Nq + kbase + lane + 16 * j]);

            float mx = fmaxf(fmaxf(s[i][0], s[i][1]), fmaxf(s[i][2], s[i][3]));
            mx = fmaxf(mx, __shfl_xor_sync(0xffffffffu, mx, 8));
            mx = fmaxf(mx, __shfl_xor_sync(0xffffffffu, mx, 4));
            mx = fmaxf(mx, __shfl_xor_sync(0xffffffffu, mx, 2));
            mx = fmaxf(mx, __shfl_xor_sync(0xffffffffu, mx, 1));
            float newm = fmaxf(mrow[i], mx);
            float alpha = __expf(mrow[i] - newm);
            mrow[i] = newm;

            float rs = 0.f;
#pragma unroll
            for (int j = 0; j < 4; j++) {
                s[i][j] = __expf(s[i][j] - newm);
                rs += s[i][j];
            }
            rs += __shfl_xor_sync(0xffffffffu, rs, 8);
            rs += __shfl_xor_sync(0xffffffffu, rs, 4);
            rs += __shfl_xor_sync(0xffffffffu, rs, 2);
            rs += __shfl_xor_sync(0xffffffffu, rs, 1);
            lrow[i] = lrow[i] * alpha + rs;

#pragma unroll
            for (int j = 0; j < 4; j++) o[i][j] *= alpha;
#pragma unroll
            for (int j = 0; j < 4; j++)
                Ps[(g + 16 * i) * PAD + lane + 16 * j] = s[i][j];
        }
        __syncthreads();

        for (int k0 = 0; k0 < 64; k0 += 4) {
            float4 p4[4];
#pragma unroll
            for (int i = 0; i < 4; i++)
                p4[i] = *(const float4*)&Ps[(g + 16 * i) * PAD + k0];
#pragma unroll
            for (int kk = 0; kk < 4; kk++) {
                float4 vv = *(const float4*)&Vs[(k0 + kk) * PAD + lane * 4];
#pragma unroll
                for (int i = 0; i < 4; i++) {
                    float pk = (kk == 0) ? p4[i].x
                             : (kk == 1) ? p4[i].y
                             : (kk == 2) ? p4[i].z
                                         : p4[i].w;
                    o[i][0] = fmaf(pk, vv.x, o[i][0]);
                    o[i][1] = fmaf(pk, vv.y, o[i][1]);
                    o[i][2] = fmaf(pk, vv.z, o[i][2]);
                    o[i][3] = fmaf(pk, vv.w, o[i][3]);
                }
            }
        }
        __syncthreads();
    }

    int bb = bh >> 4, hh = bh & 15;
#pragma unroll
    for (int i = 0; i < 4; i++) {
        float inv = 1.f / lrow[i];
        int n = qt * 64 + g + 16 * i;
        float* dst = g_ctx + ((long)(bb * Nq + n)) * Cq + hh * 64 + lane * 4;
        float4 ov = make_float4(o[i][0] * inv, o[i][1] * inv,
                                o[i][2] * inv, o[i][3] * inv);
        *(float4*)dst = ov;
    }
}

// ---------------------------------------------------------------------------
extern "C" void kernel_launch(void* const* d_in, const int* in_sizes, int n_in,
                              void* d_out, int out_size)
{
    const float* x    = (const float*)d_in[0]; // (B,N,C)
    const float* mask = (const float*)d_in[1]; // (N,N)
    const float* W    = (const float*)d_in[2]; // (3C, C)
    const float* bia  = (const float*)d_in[3]; // (3C)
    const float* ow   = (const float*)d_in[4]; // (C, C)
    const float* ob   = (const float*)d_in[5]; // (C)
    float* out = (float*)d_out;

    const int nx = Bq * Nq * Cq;      // 8388608
    const int nw = 3 * Cq * Cq;       // 3145728
    const int no = Cq * Cq;           // 1048576

    conv_split<0><<<nx / 1024, 256>>>(x, nx);
    conv_split<1><<<nw / 1024, 256>>>(W, nw);
    conv_split<2><<<no / 1024, 256>>>(ow, no);

    cudaFuncSetAttribute(attn_kernel, cudaFuncAttributeMaxDynamicSharedMemorySize, ATTN_SMEM);

    // 1) QKV projection: (8192 x 3072 x 1024) split-bf16 HMMA
    gemm_mma<1><<<dim3(3 * Cq / 128, Bq * Nq / 128), 256>>>(bia, nullptr);

    // 2) Attention (fp32 SIMT)
    attn_kernel<<<dim3(Nq / 64, Bq * Hq), 256, ATTN_SMEM>>>(mask);

    // 3) ctx -> bf16 hi/lo, then out projection (8192 x 1024 x 1024)
    conv_split<3><<<nx / 1024, 256>>>(nullptr, nx);
    gemm_mma<2><<<dim3(Cq / 128, Bq * Nq / 128), 256>>>(ob, out);
}

// round 4
// speedup vs baseline: 2.2626x; 1.6004x over previous
#include <cuda_runtime.h>
#include <cuda_bf16.h>
#include <cstdint>

#define Bq 8
#define Nq 1024
#define Cq 1024
#define Hq 16
#define Dq 64

// ---------------- scratch (static device globals; no allocation) ----------------
__device__ __align__(16) __nv_bfloat16 g_xhi[Bq * Nq * Cq],  g_xlo[Bq * Nq * Cq];
__device__ __align__(16) __nv_bfloat16 g_whi[3 * Cq * Cq],   g_wlo[3 * Cq * Cq];
__device__ __align__(16) __nv_bfloat16 g_owhi[Cq * Cq],      g_owlo[Cq * Cq];
__device__ __align__(16) __nv_bfloat16 g_chi[Bq * Nq * Cq],  g_clo[Bq * Nq * Cq];

#define QKV_ELEMS (Bq * Hq * Nq * Dq)
__device__ __align__(16) __nv_bfloat16 g_qhi[QKV_ELEMS], g_qlo[QKV_ELEMS];
__device__ __align__(16) __nv_bfloat16 g_khi[QKV_ELEMS], g_klo[QKV_ELEMS];
__device__ __align__(16) __nv_bfloat16 g_vhi[QKV_ELEMS], g_vlo[QKV_ELEMS];

// ---------------- PTX helpers ----------------
__device__ __forceinline__ uint32_t smem_u32(const void* p) {
    uint32_t a;
    asm("{ .reg .u64 t; cvta.to.shared.u64 t, %1; cvt.u32.u64 %0, t; }" : "=r"(a) : "l"(p));
    return a;
}
__device__ __forceinline__ void cp16(uint32_t dst, const void* src) {
    asm volatile("cp.async.cg.shared.global [%0], [%1], 16;" :: "r"(dst), "l"(src) : "memory");
}
__device__ __forceinline__ void cp_commit() {
    asm volatile("cp.async.commit_group;" ::: "memory");
}
template <int N>
__device__ __forceinline__ void cp_wait() {
    asm volatile("cp.async.wait_group %0;" :: "n"(N) : "memory");
}
__device__ __forceinline__ void ldsm4(uint32_t& r0, uint32_t& r1, uint32_t& r2, uint32_t& r3,
                                      uint32_t addr) {
    asm volatile("ldmatrix.sync.aligned.m8n8.x4.shared.b16 {%0,%1,%2,%3}, [%4];"
                 : "=r"(r0), "=r"(r1), "=r"(r2), "=r"(r3) : "r"(addr));
}
__device__ __forceinline__ void ldsm4t(uint32_t& r0, uint32_t& r1, uint32_t& r2, uint32_t& r3,
                                       uint32_t addr) {
    asm volatile("ldmatrix.sync.aligned.m8n8.x4.trans.shared.b16 {%0,%1,%2,%3}, [%4];"
                 : "=r"(r0), "=r"(r1), "=r"(r2), "=r"(r3) : "r"(addr));
}
__device__ __forceinline__ void mma16816(float* c, const uint32_t* a, const uint32_t* b) {
    asm volatile("mma.sync.aligned.m16n8k16.row.col.f32.bf16.bf16.f32 "
                 "{%0,%1,%2,%3}, {%4,%5,%6,%7}, {%8,%9}, {%0,%1,%2,%3};"
                 : "+f"(c[0]), "+f"(c[1]), "+f"(c[2]), "+f"(c[3])
                 : "r"(a[0]), "r"(a[1]), "r"(a[2]), "r"(a[3]), "r"(b[0]), "r"(b[1]));
}

// swizzle for 64-byte rows (GEMM tiles)
__device__ __forceinline__ uint32_t swz(int row, int cbyte) {
    return (uint32_t)(row * 64 + (cbyte ^ (((row >> 1) & 3) << 4)));
}
// swizzle for 128-byte rows (attention tiles)
__device__ __forceinline__ uint32_t swz128(int row, int cbyte) {
    return (uint32_t)(row * 128 + (cbyte ^ ((row & 7) << 4)));
}

// split fp32 pair into bf16 hi pair + lo pair (packed u32, low half = first arg)
__device__ __forceinline__ uint32_t split2(float x, float y, uint32_t& lo) {
    __nv_bfloat162 h = __floats2bfloat162_rn(x, y);
    float fx = __low2float(h), fy = __high2float(h);
    __nv_bfloat162 l = __floats2bfloat162_rn(x - fx, y - fy);
    lo = *reinterpret_cast<uint32_t*>(&l);
    return *reinterpret_cast<uint32_t*>(&h);
}

// FFMA-only exp (x <= ~0; clamps at -80); rel err ~2e-6
__device__ __forceinline__ float fexp(float x) {
    x = fmaxf(x, -80.f);
    float t = fmaf(x, 1.4426950408889634f, 12582912.f);
    int i = __float_as_int(t) - 0x4B400000;
    float fi = t - 12582912.f;
    float f = fmaf(x, 1.4426950408889634f, -fi);
    float p = 1.3333558146e-3f;
    p = fmaf(p, f, 9.6181291076e-3f);
    p = fmaf(p, f, 5.5504108665e-2f);
    p = fmaf(p, f, 2.4022650696e-1f);
    p = fmaf(p, f, 6.9314718056e-1f);
    p = fmaf(p, f, 1.0f);
    return __int_as_float(__float_as_int(p) + (i << 23));
}

// ---------------- fp32 -> bf16 hi/lo split (inputs) ----------------
// T: 0 -> x, 1 -> in_proj_weight, 2 -> out_w
template <int T>
__global__ __launch_bounds__(256) void conv_split(const float* __restrict__ src, int n)
{
    int i = (blockIdx.x * 256 + threadIdx.x) * 4;
    if (i >= n) return;
    float4 v = *(const float4*)(src + i);
    uint32_t h0, h1, l0, l1;
    h0 = split2(v.x, v.y, l0);
    h1 = split2(v.z, v.w, l1);
    __nv_bfloat16* hd = (T == 0) ? g_xhi : (T == 1) ? g_whi : g_owhi;
    __nv_bfloat16* ld = (T == 0) ? g_xlo : (T == 1) ? g_wlo : g_owlo;
    *(uint2*)(hd + i) = make_uint2(h0, h1);
    *(uint2*)(ld + i) = make_uint2(l0, l1);
}

// ---------------- mma.sync split-bf16 NT GEMM ----------------
// MODE 1: A = x (hi/lo), B = W (hi/lo), N=3072 -> scatter bf16 hi/lo q/k/v
// MODE 2: A = ctx (hi/lo), B = ow (hi/lo), N=1024 -> fp32 Cout
#define NCH2 96
#define STAGE_BYTES 16384

template <int MODE>
__global__ __launch_bounds__(256) void gemm_mma(const float* __restrict__ bias,
                                                float* __restrict__ Cout)
{
    __shared__ __align__(1024) char smem[2][STAGE_BYTES];
    const uint32_t sb = smem_u32(smem);

    const int t = threadIdx.x, wid = t >> 5, lane = t & 31;
    const int m0 = blockIdx.y * 128, n0 = blockIdx.x * 128;
    const int wm = (wid & 3) * 32, wn = (wid >> 2) * 64;
    const int gid = lane >> 2, tid = lane & 3;

    float c[2][8][4];
#pragma unroll
    for (int mi = 0; mi < 2; mi++)
#pragma unroll
        for (int nj = 0; nj < 8; nj++)
#pragma unroll
            for (int r = 0; r < 4; r++) c[mi][nj][r] = 0.f;

    auto load_stage = [&](int ch, int buf) {
        const int term = ch >> 5;
        const int kk = (ch & 31) * 32;
        const __nv_bfloat16* Asrc = (MODE == 1) ? (term < 2 ? g_xhi : g_xlo)
                                                : (term < 2 ? g_chi : g_clo);
        const __nv_bfloat16* Bsrc = (MODE == 1) ? (term == 1 ? g_wlo : g_whi)
                                                : (term == 1 ? g_owlo : g_owhi);
        uint32_t sa = sb + buf * STAGE_BYTES;
#pragma unroll
        for (int i = 0; i < 2; i++) {
            int chk = t + i * 256;
            int row = chk >> 2, ce = (chk & 3) * 8;
            cp16(sa + swz(row, ce * 2),
                 Asrc + (long)(m0 + row) * 1024 + kk + ce);
        }
#pragma unroll
        for (int i = 0; i < 2; i++) {
            int chk = t + i * 256;
            int row = chk >> 2, ce = (chk & 3) * 8;
            cp16(sa + 8192 + swz(row, ce * 2),
                 Bsrc + (long)(n0 + row) * 1024 + kk + ce);
        }
    };

    auto frag_addr = [&](uint32_t tilebase, int base_r, int kb) -> uint32_t {
        int r = base_r + (lane & 7) + ((lane >> 3) & 1) * 8;
        int cb = kb + ((lane >> 4) << 4);
        return tilebase + swz(r, cb);
    };

    load_stage(0, 0);
    cp_commit();

    for (int i = 0; i < NCH2; i++) {
        const int buf = i & 1;
        if (i + 1 < NCH2) {
            load_stage(i + 1, buf ^ 1);
            cp_commit();
            cp_wait<1>();
        } else {
            cp_wait<0>();
        }
        __syncthreads();

        const uint32_t abase = sb + buf * STAGE_BYTES;
        const uint32_t bbase = abase + 8192;
#pragma unroll
        for (int s = 0; s < 2; s++) {
            const int kb = s * 32;
            uint32_t a[2][4];
#pragma unroll
            for (int mi = 0; mi < 2; mi++)
                ldsm4(a[mi][0], a[mi][1], a[mi][2], a[mi][3],
                      frag_addr(abase, wm + mi * 16, kb));
            uint32_t b[8][2];
#pragma unroll
            for (int j = 0; j < 4; j++) {
                uint32_t r0, r1, r2, r3;
                ldsm4(r0, r1, r2, r3, frag_addr(bbase, wn + j * 16, kb));
                b[2*j][0] = r0; b[2*j][1] = r2;
                b[2*j+1][0] = r1; b[2*j+1][1] = r3;
            }
#pragma unroll
            for (int mi = 0; mi < 2; mi++)
#pragma unroll
                for (int nj = 0; nj < 8; nj++)
                    mma16816(c[mi][nj], a[mi], b[nj]);
        }
        __syncthreads();
    }

    // ---- epilogue ----
#pragma unroll
    for (int mi = 0; mi < 2; mi++) {
#pragma unroll
        for (int nj = 0; nj < 8; nj++) {
            int row = m0 + wm + mi * 16 + gid;
            int col = n0 + wn + nj * 8 + tid * 2;
            float b0 = __ldg(&bias[col]), b1 = __ldg(&bias[col + 1]);
#pragma unroll
            for (int h = 0; h < 2; h++) {
                int rr = row + h * 8;
                float vx = c[mi][nj][2*h + 0] + b0;
                float vy = c[mi][nj][2*h + 1] + b1;
                if (MODE == 1) {
                    int bb = rr >> 10, nn = rr & 1023;
                    int which = col >> 10, hh = (col >> 6) & 15, dd = col & 63;
                    long idx = ((long)(bb * Hq + hh) * Nq + nn) * Dq + dd;
                    if (which == 0) { vx *= 0.125f; vy *= 0.125f; }
                    uint32_t lo, hi = split2(vx, vy, lo);
                    __nv_bfloat16* dh = (which == 0) ? g_qhi : (which == 1) ? g_khi : g_vhi;
                    __nv_bfloat16* dl = (which == 0) ? g_qlo : (which == 1) ? g_klo : g_vlo;
                    *(uint32_t*)(dh + idx) = hi;
                    *(uint32_t*)(dl + idx) = lo;
                } else {
                    *(float2*)(Cout + (long)rr * Cq + col) = make_float2(vx, vy);
                }
            }
        }
    }
}

// ---------------- tensorized flash attention ----------------
// grid = (Nq/128, B*H), 256 threads (8 warps); warp w owns q-rows [w*16, w*16+16).
// smem: Qhi 16K | Qlo 16K | 2 stages x (Khi 8K | Klo 8K | Vhi 8K | Vlo 8K)
#define AT_SMEM (32768 + 2 * 32768)

__global__ __launch_bounds__(256) void attn_mma(const float* __restrict__ mask)
{
    extern __shared__ char sm[];
    const uint32_t sb = smem_u32(sm);
    const uint32_t QHI = 0, QLO = 16384, STG0 = 32768;

    const int t = threadIdx.x, w = t >> 5, lane = t & 31;
    const int gid = lane >> 2, tid = lane & 3;
    const int qt = blockIdx.x, bh = blockIdx.y;
    const long qoff = ((long)bh * Nq + qt * 128) * Dq;
    const long koff = (long)bh * Nq * Dq;
    const int am = w * 16;

    // Q tile loads (128 rows x 64 d, hi+lo)
#pragma unroll
    for (int i = 0; i < 4; i++) {
        int c = t + i * 256;
        int row = c >> 3, c8 = (c & 7) * 8;
        uint32_t so = swz128(row, c8 * 2);
        cp16(sb + QHI + so, g_qhi + qoff + (long)row * 64 + c8);
        cp16(sb + QLO + so, g_qlo + qoff + (long)row * 64 + c8);
    }
    auto load_kv = [&](int kt, int buf) {
        uint32_t base = sb + STG0 + buf * 32768;
        long off = koff + (long)kt * 64 * 64;
#pragma unroll
        for (int i = 0; i < 2; i++) {
            int c = t + i * 256;
            int row = c >> 3, c8 = (c & 7) * 8;
            uint32_t so = swz128(row, c8 * 2);
            long go = off + (long)row * 64 + c8;
            cp16(base + so,         g_khi + go);
            cp16(base + 8192 + so,  g_klo + go);
            cp16(base + 16384 + so, g_vhi + go);
            cp16(base + 24576 + so, g_vlo + go);
        }
    };

    load_kv(0, 0); cp_commit();
    load_kv(1, 1); cp_commit();

    float o[8][4];
#pragma unroll
    for (int j = 0; j < 8; j++)
#pragma unroll
        for (int r = 0; r < 4; r++) o[j][r] = 0.f;
    float mrow[2] = {-1e30f, -1e30f}, lrow[2] = {0.f, 0.f};

    // fragment addressing
    const int fr = (lane & 7) + ((lane >> 3) & 1) * 8;   // row within 16-block
    const int fc16 = (lane >> 4) << 4;                   // 16B column toggle
    const int vkey = (lane & 7) + (((lane >> 4) & 1) << 3);
    const int vd8  = ((lane >> 3) & 1) << 3;

    const float* mrow0 = mask + (long)(qt * 128 + am + gid) * Nq;

    for (int kt = 0; kt < 16; kt++) {
        if (kt == 15) cp_wait<0>(); else cp_wait<1>();
        __syncthreads();

        const uint32_t stg = sb + STG0 + (kt & 1) * 32768;
        const uint32_t khi_ = stg, klo_ = stg + 8192, vhi_ = stg + 16384, vlo_ = stg + 24576;

        // ---- S = Q . K^T (3 split terms) ----
        float s[8][4];
#pragma unroll
        for (int j = 0; j < 8; j++)
#pragma unroll
            for (int r = 0; r < 4; r++) s[j][r] = 0.f;

#pragma unroll
        for (int kd = 0; kd < 4; kd++) {
            const int kb = kd * 32;  // byte offset of k16 chunk
            uint32_t aq[4], aql[4], bk[8][2];
            ldsm4(aq[0], aq[1], aq[2], aq[3],
                  sb + QHI + swz128(am + fr, kb + fc16));
            ldsm4(aql[0], aql[1], aql[2], aql[3],
                  sb + QLO + swz128(am + fr, kb + fc16));
#pragma unroll
            for (int j = 0; j < 4; j++) {
                uint32_t r0, r1, r2, r3;
                ldsm4(r0, r1, r2, r3, khi_ + swz128(j * 16 + fr, kb + fc16));
                bk[2*j][0] = r0; bk[2*j][1] = r2;
                bk[2*j+1][0] = r1; bk[2*j+1][1] = r3;
            }
#pragma unroll
            for (int nj = 0; nj < 8; nj++) mma16816(s[nj], aq,  bk[nj]);
#pragma unroll
            for (int nj = 0; nj < 8; nj++) mma16816(s[nj], aql, bk[nj]);
#pragma unroll
            for (int j = 0; j < 4; j++) {
                uint32_t r0, r1, r2, r3;
                ldsm4(r0, r1, r2, r3, klo_ + swz128(j * 16 + fr, kb + fc16));
                bk[2*j][0] = r0; bk[2*j][1] = r2;
                bk[2*j+1][0] = r1; bk[2*j+1][1] = r3;
            }
#pragma unroll
            for (int nj = 0; nj < 8; nj++) mma16816(s[nj], aq, bk[nj]);
        }

        // ---- mask + online softmax ----
        const float* mp = mrow0 + kt * 64;
#pragma unroll
        for (int j = 0; j < 8; j++) {
            float2 m0 = __ldg((const float2*)(mp + j * 8 + 2 * tid));
            float2 m1 = __ldg((const float2*)(mp + 8 * Nq + j * 8 + 2 * tid));
            s[j][0] += m0.x; s[j][1] += m0.y;
            s[j][2] += m1.x; s[j][3] += m1.y;
        }
        float mx0 = -1e30f, mx1 = -1e30f;
#pragma unroll
        for (int j = 0; j < 8; j++) {
            mx0 = fmaxf(mx0, fmaxf(s[j][0], s[j][1]));
            mx1 = fmaxf(mx1, fmaxf(s[j][2], s[j][3]));
        }
        mx0 = fmaxf(mx0, __shfl_xor_sync(0xffffffffu, mx0, 1));
        mx0 = fmaxf(mx0, __shfl_xor_sync(0xffffffffu, mx0, 2));
        mx1 = fmaxf(mx1, __shfl_xor_sync(0xffffffffu, mx1, 1));
        mx1 = fmaxf(mx1, __shfl_xor_sync(0xffffffffu, mx1, 2));
        float nm0 = fmaxf(mrow[0], mx0), nm1 = fmaxf(mrow[1], mx1);
        float al0 = fexp(mrow[0] - nm0), al1 = fexp(mrow[1] - nm1);
        mrow[0] = nm0; mrow[1] = nm1;

        float rs0 = 0.f, rs1 = 0.f;
#pragma unroll
        for (int j = 0; j < 8; j++) {
            s[j][0] = fexp(s[j][0] - nm0);
            s[j][1] = fexp(s[j][1] - nm0);
            s[j][2] = fexp(s[j][2] - nm1);
            s[j][3] = fexp(s[j][3] - nm1);
            rs0 += s[j][0] + s[j][1];
            rs1 += s[j][2] + s[j][3];
        }
        rs0 += __shfl_xor_sync(0xffffffffu, rs0, 1);
        rs0 += __shfl_xor_sync(0xffffffffu, rs0, 2);
        rs1 += __shfl_xor_sync(0xffffffffu, rs1, 1);
        rs1 += __shfl_xor_sync(0xffffffffu, rs1, 2);
        lrow[0] = lrow[0] * al0 + rs0;
        lrow[1] = lrow[1] * al1 + rs1;
#pragma unroll
        for (int j = 0; j < 8; j++) {
            o[j][0] *= al0; o[j][1] *= al0;
            o[j][2] *= al1; o[j][3] *= al1;
        }

        // ---- P fragments (A layout), hi/lo split ----
        uint32_t pah[4][4], pal[4][4];
#pragma unroll
        for (int ck = 0; ck < 4; ck++) {
            pah[ck][0] = split2(s[2*ck][0],   s[2*ck][1],   pal[ck][0]);
            pah[ck][1] = split2(s[2*ck][2],   s[2*ck][3],   pal[ck][1]);
            pah[ck][2] = split2(s[2*ck+1][0], s[2*ck+1][1], pal[ck][2]);
            pah[ck][3] = split2(s[2*ck+1][2], s[2*ck+1][3], pal[ck][3]);
        }

        // ---- O += P . V (3 split terms), V via ldmatrix.trans ----
#pragma unroll
        for (int ck = 0; ck < 4; ck++) {
            const int k0 = ck * 16;
            uint32_t bv[8][2];
#pragma unroll
            for (int j = 0; j < 4; j++) {   // Vhi
                uint32_t r0, r1, r2, r3;
                ldsm4t(r0, r1, r2, r3, vhi_ + swz128(k0 + vkey, (j * 16 + vd8) * 2));
                bv[2*j][0] = r0; bv[2*j][1] = r2;
                bv[2*j+1][0] = r1; bv[2*j+1][1] = r3;
            }
#pragma unroll
            for (int nj = 0; nj < 8; nj++) mma16816(o[nj], pah[ck], bv[nj]);
#pragma unroll
            for (int nj = 0; nj < 8; nj++) mma16816(o[nj], pal[ck], bv[nj]);
#pragma unroll
            for (int j = 0; j < 4; j++) {   // Vlo
                uint32_t r0, r1, r2, r3;
                ldsm4t(r0, r1, r2, r3, vlo_ + swz128(k0 + vkey, (j * 16 + vd8) * 2));
                bv[2*j][0] = r0; bv[2*j][1] = r2;
                bv[2*j+1][0] = r1; bv[2*j+1][1] = r3;
            }
#pragma unroll
            for (int nj = 0; nj < 8; nj++) mma16816(o[nj], pah[ck], bv[nj]);
        }

        __syncthreads();
        if (kt + 2 < 16) { load_kv(kt + 2, kt & 1); cp_commit(); }
        else cp_commit();   // keep group counting consistent
    }

    // ---- epilogue: ctx (B, N, H*D) as bf16 hi/lo ----
    const int bb = bh >> 4, hh = bh & 15;
    const float inv0 = 1.f / lrow[0], inv1 = 1.f / lrow[1];
    const int n0r = qt * 128 + am + gid;
#pragma unroll
    for (int j = 0; j < 8; j++) {
        int d = hh * 64 + j * 8 + 2 * tid;
        long i0 = ((long)(bb * Nq + n0r)) * Cq + d;
        long i1 = ((long)(bb * Nq + n0r + 8)) * Cq + d;
        uint32_t lo, hi;
        hi = split2(o[j][0] * inv0, o[j][1] * inv0, lo);
        *(uint32_t*)(g_chi + i0) = hi; *(uint32_t*)(g_clo + i0) = lo;
        hi = split2(o[j][2] * inv1, o[j][3] * inv1, lo);
        *(uint32_t*)(g_chi + i1) = hi; *(uint32_t*)(g_clo + i1) = lo;
    }
}

// ---------------------------------------------------------------------------
extern "C" void kernel_launch(void* const* d_in, const int* in_sizes, int n_in,
                              void* d_out, int out_size)
{
    const float* x    = (const float*)d_in[0]; // (B,N,C)
    const float* mask = (const float*)d_in[1]; // (N,N)
    const float* W    = (const float*)d_in[2]; // (3C, C)
    const float* bia  = (const float*)d_in[3]; // (3C)
    const float* ow   = (const float*)d_in[4]; // (C, C)
    const float* ob   = (const float*)d_in[5]; // (C)
    float* out = (float*)d_out;

    const int nx = Bq * Nq * Cq;
    const int nw = 3 * Cq * Cq;
    const int no = Cq * Cq;

    conv_split<0><<<nx / 1024, 256>>>(x, nx);
    conv_split<1><<<nw / 1024, 256>>>(W, nw);
    conv_split<2><<<no / 1024, 256>>>(ow, no);

    cudaFuncSetAttribute(attn_mma, cudaFuncAttributeMaxDynamicSharedMemorySize, AT_SMEM);

    // 1) QKV projection -> bf16 hi/lo q/k/v
    gemm_mma<1><<<dim3(3 * Cq / 128, Bq * Nq / 128), 256>>>(bia, nullptr);

    // 2) Tensorized flash attention -> bf16 hi/lo ctx
    attn_mma<<<dim3(Nq / 128, Bq * Hq), 256, AT_SMEM>>>(mask);

    // 3) Output projection -> fp32 out
    gemm_mma<2><<<dim3(Cq / 128, Bq * Nq / 128), 256>>>(ob, out);
}